// round 2
// baseline (speedup 1.0000x reference)
#include <cuda_runtime.h>
#include <math.h>

#define BB 32
#define SS 512
#define HH 768
#define NSNS 4096
#define WE 150
#define LL 9
#define NPOS (BB*SS)        // 16384
#define NSPANS (BB*NSNS)    // 131072
#define T_STRIDE 304
#define WD_STRIDE 152

// scratch (static device globals; no allocation in kernel_launch)
__device__ float g_T[NPOS * T_STRIDE];     // [pos][0:150]=start-part, [150:300]=end-part
__device__ float g_WD[16 * WD_STRIDE];     // width contribution + b1 folded in
__device__ int   g_used[NPOS];
__device__ int   g_list[NPOS];
__device__ int   g_count;

__global__ void k_init(float* loss_ptr) {
    int i = blockIdx.x * blockDim.x + threadIdx.x;
    if (i < NPOS) g_used[i] = 0;
    if (i == 0) { g_count = 0; *loss_ptr = 0.f; }
}

__global__ void k_mark(const int* __restrict__ spans) {
    int i = blockIdx.x * blockDim.x + threadIdx.x;
    if (i >= NSPANS) return;
    int b = i >> 12;
    int s = spans[3*i];
    int e = spans[3*i + 1];
    s = min(max(s, 0), SS-1);
    e = min(max(e, 0), SS-1);
    g_used[(b << 9) + s] = 1;
    g_used[(b << 9) + e] = 1;
}

__global__ void k_compact() {
    int i = blockIdx.x * blockDim.x + threadIdx.x;
    if (i < NPOS && g_used[i]) {
        int slot = atomicAdd(&g_count, 1);
        g_list[slot] = i;
    }
}

// One CTA per used position: T[row][j]    = sum_k relu(seq[row][k]) * W1[k][j]
//                            T[row][150+j]= sum_k relu(seq[row][k]) * W1[768+k][j]
__global__ void k_T(const float* __restrict__ seq, const float* __restrict__ W1) {
    if ((int)blockIdx.x >= g_count) return;
    int row = g_list[blockIdx.x];
    __shared__ float sSeq[HH];
    int tid = threadIdx.x;
    for (int k = tid; k < HH; k += blockDim.x)
        sSeq[k] = fmaxf(seq[(size_t)row * HH + k], 0.f);
    __syncthreads();
    if (tid < WE) {
        float a0 = 0.f, a1 = 0.f;
        #pragma unroll 4
        for (int k = 0; k < HH; k++) {
            float v = sSeq[k];
            a0 = fmaf(v, W1[k * WE + tid], a0);
            a1 = fmaf(v, W1[(HH + k) * WE + tid], a1);
        }
        g_T[row * T_STRIDE + tid] = a0;
        g_T[row * T_STRIDE + WE + tid] = a1;
    }
}

// WD[w][j] = b1[j] + sum_k relu(width_table[w][k]) * W1[1536+k][j]
__global__ void k_WD(const float* __restrict__ wt, const float* __restrict__ W1,
                     const float* __restrict__ b1) {
    extern __shared__ float sm[];
    float* sW  = sm;                 // [150*150] width part of W1, [k][j]
    float* sWT = sm + WE*WE;         // [9*150] relu(width_table)
    float* sB1 = sWT + 9*WE;         // [150]
    int tid = threadIdx.x;
    for (int idx = tid; idx < WE*WE; idx += blockDim.x) sW[idx] = W1[2*HH*WE + idx];
    for (int idx = tid; idx < 9*WE; idx += blockDim.x) sWT[idx] = fmaxf(wt[idx], 0.f);
    for (int idx = tid; idx < WE;   idx += blockDim.x) sB1[idx] = b1[idx];
    __syncthreads();
    for (int idx = tid; idx < 9*WE; idx += blockDim.x) {
        int w = idx / WE, j = idx - w*WE;
        float acc = sB1[j];
        #pragma unroll 5
        for (int k = 0; k < WE; k++)
            acc = fmaf(sWT[w*WE + k], sW[k*WE + j], acc);
        g_WD[w * WD_STRIDE + j] = acc;
    }
}

// Fused stage 2: gather h1 -> @W2 (+b2) -> @W3 (+b3) -> logits + NLL loss
// 128 spans per CTA, 256 threads, W2/W3 in smem.
#define TM 128
__global__ void __launch_bounds__(256, 1)
k_main(const int* __restrict__ spans,
       const int* __restrict__ mask,
       const int* __restrict__ label,
       const float* __restrict__ W2, const float* __restrict__ b2,
       const float* __restrict__ W3, const float* __restrict__ b3,
       float* __restrict__ out)
{
    extern __shared__ float sm[];
    float* sW2  = sm;                      // [150][160]  (cols 150..159 zero)
    float* sU   = sm + 24000;              // union: h1T [k<152][128] / h2 [128][164]
    float* sW3  = sm + 44992;              // [150][12]   (cols 9..11 zero)
    float* sB2  = sm + 46792;              // [160]
    float* sB3  = sm + 46952;              // [12]
    float* sLog = sm + 46964;              // [128][12]
    int*   sPS  = (int*)(sm + 48500);
    int*   sPE  = sPS + TM;
    int*   sWd  = sPE + TM;
    int*   sMk  = sWd + TM;
    int*   sLb  = sMk + TM;
    float* sLoss = (float*)(sLb + TM);

    int tid = threadIdx.x;
    int base = blockIdx.x * TM;

    if (tid < TM) {
        int i = base + tid;
        int s = spans[3*i], e = spans[3*i + 1], w = spans[3*i + 2];
        int si = min(max(s, 0), SS-1);
        int ei = min(max(e, 0), SS-1);
        int wi = min(max(w, 0), 8);
        int b = i >> 12;
        sPS[tid] = (b << 9) + si;
        sPE[tid] = (b << 9) + ei;
        sWd[tid] = wi;
        sMk[tid] = mask[i];
        sLb[tid] = min(max(label[i], 0), LL-1);
    }
    if (tid == 0) *sLoss = 0.f;

    for (int idx = tid; idx < 150*160; idx += 256) {
        int k = idx / 160, j = idx - k*160;
        sW2[idx] = (j < 150) ? W2[k*150 + j] : 0.f;
    }
    for (int idx = tid; idx < 150*12; idx += 256) {
        int k = idx / 12, l = idx - k*12;
        sW3[idx] = (l < 9) ? W3[k*9 + l] : 0.f;
    }
    if (tid < 160) sB2[tid] = (tid < 150) ? b2[tid] : 0.f;
    if (tid < 12)  sB3[tid] = (tid < 9)  ? b3[tid] : 0.f;
    __syncthreads();

    // build h1 tile, k-major: sU[k*128 + r]
    for (int idx = tid; idx < 150*TM; idx += 256) {
        int k = idx >> 7, r = idx & 127;
        float v = g_T[sPS[r]*T_STRIDE + k]
                + g_T[sPE[r]*T_STRIDE + WE + k]
                + g_WD[sWd[r]*WD_STRIDE + k];
        sU[idx] = fmaxf(v, 0.f);
    }
    __syncthreads();

    // h2 = h1 @ W2 : per-thread 8 rows x 10 cols
    int tr = tid >> 4, tc = tid & 15;
    int r0 = tr * 8, c0 = tc * 10;
    float acc[8][10];
    #pragma unroll
    for (int ri = 0; ri < 8; ri++)
        #pragma unroll
        for (int ci = 0; ci < 10; ci++)
            acc[ri][ci] = 0.f;

    #pragma unroll 2
    for (int k = 0; k < 150; k++) {
        float4 a0 = *(const float4*)&sU[k*128 + r0];
        float4 a1 = *(const float4*)&sU[k*128 + r0 + 4];
        float av[8] = {a0.x, a0.y, a0.z, a0.w, a1.x, a1.y, a1.z, a1.w};
        const float* wrow = &sW2[k*160 + c0];
        float bv[10];
        #pragma unroll
        for (int ci = 0; ci < 5; ci++) {
            float2 t = *(const float2*)&wrow[2*ci];
            bv[2*ci] = t.x; bv[2*ci+1] = t.y;
        }
        #pragma unroll
        for (int ri = 0; ri < 8; ri++)
            #pragma unroll
            for (int ci = 0; ci < 10; ci++)
                acc[ri][ci] = fmaf(av[ri], bv[ci], acc[ri][ci]);
    }
    __syncthreads();   // all h1 reads done

    // write h2 (+b2) into sU as [r][164]
    #pragma unroll
    for (int ri = 0; ri < 8; ri++)
        #pragma unroll
        for (int ci = 0; ci < 10; ci++)
            sU[(r0 + ri)*164 + c0 + ci] = acc[ri][ci] + sB2[c0 + ci];
    __syncthreads();

    // logits = h2 @ W3 + b3
    for (int idx = tid; idx < TM*LL; idx += 256) {
        int r = idx / LL, l = idx - r*LL;
        float a = sB3[l];
        #pragma unroll 5
        for (int k = 0; k < 150; k++)
            a = fmaf(sU[r*164 + k], sW3[k*12 + l], a);
        sLog[r*12 + l] = a;
        out[(size_t)(base + r)*LL + l] = a;
    }
    __syncthreads();

    // loss: sum over active spans of (lse - logit[label])
    if (tid < TM) {
        if (sMk[tid] == 1) {
            float m = -1e30f;
            #pragma unroll
            for (int l = 0; l < LL; l++) m = fmaxf(m, sLog[tid*12 + l]);
            float ssum = 0.f;
            #pragma unroll
            for (int l = 0; l < LL; l++) ssum += expf(sLog[tid*12 + l] - m);
            float lse = m + logf(ssum);
            atomicAdd(sLoss, lse - sLog[tid*12 + sLb[tid]]);
        }
    }
    __syncthreads();
    if (tid == 0) atomicAdd(&out[(size_t)NSPANS * LL], *sLoss);
}

extern "C" void kernel_launch(void* const* d_in, const int* in_sizes, int n_in,
                              void* d_out, int out_size) {
    const float* seq   = (const float*)d_in[0];
    const float* wt    = (const float*)d_in[1];
    const float* W1    = (const float*)d_in[2];
    const float* b1    = (const float*)d_in[3];
    const float* W2    = (const float*)d_in[4];
    const float* b2    = (const float*)d_in[5];
    const float* W3    = (const float*)d_in[6];
    const float* b3    = (const float*)d_in[7];
    const int* spans = (const int*)d_in[8];
    const int* smask = (const int*)d_in[9];
    const int* slab  = (const int*)d_in[10];
    float* out = (float*)d_out;

    static const size_t SMEM_WD   = (size_t)(WE*WE + 9*WE + WE) * 4;   // 96000
    static const size_t SMEM_MAIN = (size_t)49152 * 4;                 // 196608

    cudaFuncSetAttribute(k_WD,   cudaFuncAttributeMaxDynamicSharedMemorySize, (int)SMEM_WD);
    cudaFuncSetAttribute(k_main, cudaFuncAttributeMaxDynamicSharedMemorySize, (int)SMEM_MAIN);

    k_init<<<NPOS/256, 256>>>(out + (size_t)NSPANS * LL);
    k_mark<<<NSPANS/256, 256>>>(spans);
    k_compact<<<NPOS/256, 256>>>();
    k_T<<<NPOS, 256>>>(seq, W1);
    k_WD<<<1, 256, SMEM_WD>>>(wt, W1, b1);
    k_main<<<NSPANS/TM, 256, SMEM_MAIN>>>(spans, smask, slab, W2, b2, W3, b3, out);
}

// round 3
// speedup vs baseline: 2.5967x; 2.5967x over previous
#include <cuda_runtime.h>
#include <math.h>

#define BB 32
#define SS 512
#define HH 768
#define WE 150
#define LL 9
#define NPOS (BB*SS)            // 16384
#define NSPANS (BB*4096)        // 131072
#define T_STRIDE 304
#define WD_STRIDE 152
#define RANKCAP 64
#define KEYS_PER_B (RANKCAP*RANKCAP*9)   // 36864
#define NKEYS (BB*KEYS_PER_B)            // 1179648

// static scratch (no allocation anywhere)
__device__ float    g_A[NPOS*HH];           // relu(seq) gathered, slot-indexed
__device__ float    g_T[NPOS*T_STRIDE];     // [slot][0:150]=start part,[150:300]=end part
__device__ float    g_WD[16*WD_STRIDE];     // width part + b1
__device__ float    g_ULOG[(size_t)NSPANS*12];  // unique logits
__device__ int      g_used[NPOS];
__device__ int      g_list[NPOS];
__device__ int      g_slotOfPos[NPOS];
__device__ int      g_rank[NPOS];
__device__ int      g_bcount[BB];
__device__ int      g_count;
__device__ int      g_ckey[NKEYS];          // claim table (-1 / owner span id)
__device__ int      g_uslot[NKEYS];         // key -> unique slot
__device__ int      g_key[NSPANS];          // per-span key, or -2 (direct)
__device__ int      g_spanslot[NSPANS];     // slot for direct spans
__device__ unsigned g_uinfo[NSPANS];        // packed (slot_s | slot_e<<14 | w<<28)
__device__ int      g_ucount;

__device__ __forceinline__ int clampi(int v, int lo, int hi) {
    return min(max(v, lo), hi);
}

__global__ void k_init(float* loss_ptr) {
    int i = blockIdx.x * blockDim.x + threadIdx.x;
    if (i < NKEYS) g_ckey[i] = -1;
    if (i < NPOS) g_used[i] = 0;
    if (i < BB) g_bcount[i] = 0;
    if (i == 0) { g_count = 0; g_ucount = 0; *loss_ptr = 0.f; }
}

__global__ void k_mark(const int* __restrict__ spans) {
    int i = blockIdx.x * blockDim.x + threadIdx.x;
    if (i >= NSPANS) return;
    int b = i >> 12;
    int s = clampi(spans[3*i], 0, SS-1);
    int e = clampi(spans[3*i + 1], 0, SS-1);
    g_used[(b << 9) + s] = 1;
    g_used[(b << 9) + e] = 1;
}

__global__ void k_compact() {
    int i = blockIdx.x * blockDim.x + threadIdx.x;
    if (i < NPOS && g_used[i]) {
        int slot = atomicAdd(&g_count, 1);
        g_list[slot] = i;
        g_slotOfPos[i] = slot;
        g_rank[i] = atomicAdd(&g_bcount[i >> 9], 1);
    }
}

__global__ void k_assign(const int* __restrict__ spans) {
    int i = blockIdx.x * blockDim.x + threadIdx.x;
    if (i >= NSPANS) return;
    int b = i >> 12;
    int si = clampi(spans[3*i], 0, SS-1);
    int ei = clampi(spans[3*i + 1], 0, SS-1);
    int wi = clampi(spans[3*i + 2], 0, 8);
    int rs = g_rank[(b << 9) + si];
    int re = g_rank[(b << 9) + ei];
    int key;
    if (rs < RANKCAP && re < RANKCAP) {
        key = b * KEYS_PER_B + (rs * RANKCAP + re) * 9 + wi;
        atomicCAS(&g_ckey[key], -1, i);
    } else {
        key = -2;
    }
    g_key[i] = key;
}

__global__ void k_own(const int* __restrict__ spans) {
    int i = blockIdx.x * blockDim.x + threadIdx.x;
    if (i >= NSPANS) return;
    int key = g_key[i];
    bool own = (key == -2) || (g_ckey[key] == i);
    if (!own) return;
    int b = i >> 12;
    int si = clampi(spans[3*i], 0, SS-1);
    int ei = clampi(spans[3*i + 1], 0, SS-1);
    int wi = clampi(spans[3*i + 2], 0, 8);
    int ss = g_slotOfPos[(b << 9) + si];
    int se = g_slotOfPos[(b << 9) + ei];
    int slot = atomicAdd(&g_ucount, 1);
    g_uinfo[slot] = (unsigned)ss | ((unsigned)se << 14) | ((unsigned)wi << 28);
    if (key >= 0) g_uslot[key] = slot;
    else g_spanslot[i] = slot;
}

// gather relu(seq) for used rows into g_A (slot-indexed) and zero g_T rows
__global__ void k_prep(const float* __restrict__ seq) {
    int cnt = g_count;
    for (int slot = blockIdx.x; slot < cnt; slot += gridDim.x) {
        int pos = g_list[slot];
        const float* src = seq + (size_t)pos * HH;
        for (int t = threadIdx.x; t < HH; t += blockDim.x)
            g_A[slot * HH + t] = fmaxf(src[t], 0.f);
        for (int t = threadIdx.x; t < T_STRIDE; t += blockDim.x)
            g_T[slot * T_STRIDE + t] = 0.f;
    }
}

// T[slot][jj] (+=) over k-chunks: tile = 8 rows x 300 cols x 192 k
__global__ void __launch_bounds__(320)
k_Tgemm(const float* __restrict__ W1) {
    __shared__ float sA[8 * 192];
    int cnt = g_count;
    int ntasks = ((cnt + 7) >> 3) * 4;
    int tid = threadIdx.x;
    int jj = tid;
    const float* wp = (jj < 150) ? (W1 + jj) : (W1 + HH * WE + (jj - 150));

    for (int task = blockIdx.x; task < ntasks; task += gridDim.x) {
        int rt = task >> 2, ks = task & 3;
        int r0 = rt * 8, k0 = ks * 192;
        for (int idx = tid; idx < 8 * 192; idx += 320) {
            int lr = idx / 192, lk = idx - lr * 192;
            int row = r0 + lr;
            sA[idx] = (row < cnt) ? g_A[row * HH + k0 + lk] : 0.f;
        }
        __syncthreads();
        if (jj < 300) {
            float acc[8];
            #pragma unroll
            for (int r = 0; r < 8; r++) acc[r] = 0.f;
            #pragma unroll 4
            for (int k = 0; k < 192; k++) {
                float w1 = wp[(size_t)(k0 + k) * WE];
                #pragma unroll
                for (int r = 0; r < 8; r++)
                    acc[r] = fmaf(sA[r * 192 + k], w1, acc[r]);
            }
            int rmax = min(8, cnt - r0);
            for (int r = 0; r < rmax; r++)
                atomicAdd(&g_T[(r0 + r) * T_STRIDE + jj], acc[r]);
        }
        __syncthreads();
    }
}

// WD[w][j] = b1[j] + sum_k relu(width_table[w][k]) * W1[1536+k][j]
__global__ void k_WD(const float* __restrict__ wt, const float* __restrict__ W1,
                     const float* __restrict__ b1) {
    extern __shared__ float sm[];
    float* sW  = sm;
    float* sWT = sm + WE*WE;
    float* sB1 = sWT + 9*WE;
    int tid = threadIdx.x;
    for (int idx = tid; idx < WE*WE; idx += blockDim.x) sW[idx] = W1[2*HH*WE + idx];
    for (int idx = tid; idx < 9*WE; idx += blockDim.x) sWT[idx] = fmaxf(wt[idx], 0.f);
    for (int idx = tid; idx < WE;   idx += blockDim.x) sB1[idx] = b1[idx];
    __syncthreads();
    for (int idx = tid; idx < 9*WE; idx += blockDim.x) {
        int w = idx / WE, j = idx - w*WE;
        float acc = sB1[j];
        #pragma unroll 5
        for (int k = 0; k < WE; k++)
            acc = fmaf(sWT[w*WE + k], sW[k*WE + j], acc);
        g_WD[w * WD_STRIDE + j] = acc;
    }
}

// unique rows: gather h1 -> @W2+b2 -> @W3+b3 -> g_ULOG
__global__ void __launch_bounds__(256, 1)
k_uniq(const float* __restrict__ W2, const float* __restrict__ b2,
       const float* __restrict__ W3, const float* __restrict__ b3)
{
    extern __shared__ float sm[];
    float* sW2 = sm;                   // [150][160]
    float* sU  = sm + 24000;           // union h1T [k][128] / h2 [128][164]
    float* sW3 = sm + 44992;           // [150][12]
    float* sB2 = sm + 46792;
    float* sB3 = sm + 46952;
    unsigned* sInfo = (unsigned*)(sm + 46964);  // [128]
    int tid = threadIdx.x;

    for (int idx = tid; idx < 150*160; idx += 256) {
        int k = idx / 160, j = idx - k*160;
        sW2[idx] = (j < 150) ? W2[k*150 + j] : 0.f;
    }
    for (int idx = tid; idx < 150*12; idx += 256) {
        int k = idx / 12, l = idx - k*12;
        sW3[idx] = (l < 9) ? W3[k*9 + l] : 0.f;
    }
    if (tid < 160) sB2[tid] = (tid < 150) ? b2[tid] : 0.f;
    if (tid < 12)  sB3[tid] = (tid < 9)  ? b3[tid] : 0.f;

    int nu = g_ucount;
    int tr = tid >> 4, tc = tid & 15;
    int r0 = tr * 8, c0 = tc * 10;

    for (int base = blockIdx.x * 128; base < nu; base += gridDim.x * 128) {
        if (tid < 128)
            sInfo[tid] = (base + tid < nu) ? g_uinfo[base + tid] : 0u;
        __syncthreads();

        for (int idx = tid; idx < 150*128; idx += 256) {
            int k = idx >> 7, r = idx & 127;
            unsigned info = sInfo[r];
            int ss = info & 0x3FFF, se = (info >> 14) & 0x3FFF, w = info >> 28;
            float v = g_T[ss*T_STRIDE + k] + g_T[se*T_STRIDE + 150 + k]
                    + g_WD[w*WD_STRIDE + k];
            sU[idx] = fmaxf(v, 0.f);
        }
        __syncthreads();

        float acc[8][10];
        #pragma unroll
        for (int ri = 0; ri < 8; ri++)
            #pragma unroll
            for (int ci = 0; ci < 10; ci++)
                acc[ri][ci] = 0.f;

        #pragma unroll 2
        for (int k = 0; k < 150; k++) {
            float4 a0 = *(const float4*)&sU[k*128 + r0];
            float4 a1 = *(const float4*)&sU[k*128 + r0 + 4];
            float av[8] = {a0.x, a0.y, a0.z, a0.w, a1.x, a1.y, a1.z, a1.w};
            const float* wrow = &sW2[k*160 + c0];
            float bv[10];
            #pragma unroll
            for (int ci = 0; ci < 5; ci++) {
                float2 t = *(const float2*)&wrow[2*ci];
                bv[2*ci] = t.x; bv[2*ci+1] = t.y;
            }
            #pragma unroll
            for (int ri = 0; ri < 8; ri++)
                #pragma unroll
                for (int ci = 0; ci < 10; ci++)
                    acc[ri][ci] = fmaf(av[ri], bv[ci], acc[ri][ci]);
        }
        __syncthreads();

        #pragma unroll
        for (int ri = 0; ri < 8; ri++)
            #pragma unroll
            for (int ci = 0; ci < 10; ci++)
                sU[(r0 + ri)*164 + c0 + ci] = acc[ri][ci] + sB2[c0 + ci];
        __syncthreads();

        for (int idx = tid; idx < 128*LL; idx += 256) {
            int r = idx / LL, l = idx - r*LL;
            float a = sB3[l];
            #pragma unroll 5
            for (int k = 0; k < 150; k++)
                a = fmaf(sU[r*164 + k], sW3[k*12 + l], a);
            if (base + r < nu)
                g_ULOG[(size_t)(base + r)*12 + l] = a;
        }
        __syncthreads();
    }
}

// per-span: copy logits from unique row, accumulate NLL loss
__global__ void k_scatter(const int* __restrict__ mask,
                          const int* __restrict__ label,
                          float* __restrict__ out)
{
    __shared__ float sL;
    if (threadIdx.x == 0) sL = 0.f;
    __syncthreads();
    int i = blockIdx.x * blockDim.x + threadIdx.x;
    float contrib = 0.f;
    if (i < NSPANS) {
        int key = g_key[i];
        int slot = (key >= 0) ? g_uslot[key] : g_spanslot[i];
        const float* Lr = &g_ULOG[(size_t)slot * 12];
        float4 p0 = *(const float4*)Lr;
        float4 p1 = *(const float4*)(Lr + 4);
        float l8 = Lr[8];
        float L[9] = {p0.x, p0.y, p0.z, p0.w, p1.x, p1.y, p1.z, p1.w, l8};
        float* o = out + (size_t)i * LL;
        #pragma unroll
        for (int l = 0; l < LL; l++) o[l] = L[l];
        if (mask[i] == 1) {
            float m = L[0];
            #pragma unroll
            for (int l = 1; l < LL; l++) m = fmaxf(m, L[l]);
            float ssum = 0.f;
            #pragma unroll
            for (int l = 0; l < LL; l++) ssum += expf(L[l] - m);
            int lb = clampi(label[i], 0, LL-1);
            contrib = (m + logf(ssum)) - L[lb];
        }
    }
    atomicAdd(&sL, contrib);
    __syncthreads();
    if (threadIdx.x == 0 && sL != 0.f)
        atomicAdd(&out[(size_t)NSPANS * LL], sL);
}

extern "C" void kernel_launch(void* const* d_in, const int* in_sizes, int n_in,
                              void* d_out, int out_size) {
    const float* seq = (const float*)d_in[0];
    const float* wt  = (const float*)d_in[1];
    const float* W1  = (const float*)d_in[2];
    const float* b1  = (const float*)d_in[3];
    const float* W2  = (const float*)d_in[4];
    const float* b2  = (const float*)d_in[5];
    const float* W3  = (const float*)d_in[6];
    const float* b3  = (const float*)d_in[7];
    const int* spans = (const int*)d_in[8];
    const int* smask = (const int*)d_in[9];
    const int* slab  = (const int*)d_in[10];
    float* out = (float*)d_out;

    static const size_t SMEM_WD   = (size_t)(WE*WE + 9*WE + WE) * 4;    // 96000
    static const size_t SMEM_UNIQ = (size_t)(46964 + 128) * 4;          // 188368

    cudaFuncSetAttribute(k_WD,   cudaFuncAttributeMaxDynamicSharedMemorySize, (int)SMEM_WD);
    cudaFuncSetAttribute(k_uniq, cudaFuncAttributeMaxDynamicSharedMemorySize, (int)SMEM_UNIQ);

    k_init<<<NKEYS/256, 256>>>(out + (size_t)NSPANS * LL);
    k_mark<<<NSPANS/256, 256>>>(spans);
    k_compact<<<NPOS/256, 256>>>();
    k_assign<<<NSPANS/256, 256>>>(spans);
    k_own<<<NSPANS/256, 256>>>(spans);
    k_prep<<<512, 256>>>(seq);
    k_Tgemm<<<296, 320>>>(W1);
    k_WD<<<1, 256, SMEM_WD>>>(wt, W1, b1);
    k_uniq<<<296, 256, SMEM_UNIQ>>>(W2, b2, W3, b3);
    k_scatter<<<NSPANS/256, 256>>>(smask, slab, out);
}

// round 4
// speedup vs baseline: 3.8793x; 1.4939x over previous
#include <cuda_runtime.h>
#include <math.h>

#define BB 32
#define SS 512
#define HH 768
#define WE 150
#define LL 9
#define NPOS (BB*SS)            // 16384
#define NSPANS (BB*4096)        // 131072
#define T_STRIDE 304            // [0:150]=start part, [152:302]=end part
#define WD_STRIDE 152
#define RANKCAP 32
#define KEYS_PER_B (RANKCAP*RANKCAP*9)   // 9216
#define NKEYS (BB*KEYS_PER_B)            // 294912

// static scratch; all zero-initialized at load. Invariant maintained by the
// pipeline itself: every array is restored to its entry state each call.
__device__ float    g_A[NPOS*HH];
__device__ float    g_T[NPOS*T_STRIDE];
__device__ float    g_WD[16*WD_STRIDE];
__device__ float    g_ULOG[(size_t)NSPANS*12];
__device__ int      g_used[NPOS];       // cleared by k_compact after read
__device__ int      g_list[NPOS];
__device__ int      g_slotOfPos[NPOS];
__device__ int      g_rank[NPOS];
__device__ int      g_bcount[BB];       // reset by k_scatter
__device__ int      g_count;            // reset by k_scatter
__device__ int      g_ckey[NKEYS];      // 0=empty, owner=i+1; cleared by k_scatter
__device__ int      g_uslot[NKEYS];
__device__ int      g_key[NSPANS];
__device__ int      g_spanslot[NSPANS];
__device__ unsigned g_uinfo[NSPANS];
__device__ int      g_ucount;           // reset by k_scatter

__device__ __forceinline__ int clampi(int v, int lo, int hi) { return min(max(v, lo), hi); }

__device__ __forceinline__ unsigned long long ffma2(unsigned long long a,
                                                    unsigned long long b,
                                                    unsigned long long c) {
    unsigned long long d;
    asm("fma.rn.f32x2 %0, %1, %2, %3;" : "=l"(d) : "l"(a), "l"(b), "l"(c));
    return d;
}
__device__ __forceinline__ unsigned long long pack2(float x) {
    unsigned long long d;
    asm("mov.b64 %0, {%1, %1};" : "=l"(d) : "f"(x));
    return d;
}

// K1: mark used positions + zero loss
__global__ void k_mark(const int* __restrict__ spans, float* __restrict__ loss_ptr) {
    int i = blockIdx.x * blockDim.x + threadIdx.x;
    if (i == 0) *loss_ptr = 0.f;
    if (i >= NSPANS) return;
    int b = i >> 12;
    int s = clampi(spans[3*i], 0, SS-1);
    int e = clampi(spans[3*i + 1], 0, SS-1);
    g_used[(b << 9) + s] = 1;
    g_used[(b << 9) + e] = 1;
}

// K2: compact used positions (and self-clear g_used)
__global__ void k_compact() {
    int i = blockIdx.x * blockDim.x + threadIdx.x;
    if (i >= NPOS) return;
    if (g_used[i]) {
        int slot = atomicAdd(&g_count, 1);
        g_list[slot] = i;
        g_slotOfPos[i] = slot;
        g_rank[i] = atomicAdd(&g_bcount[i >> 9], 1);
        g_used[i] = 0;
    }
}

// K3: blocks [0,512): claim (CAS winner owns + allocates unique slot)
//     blocks [512,576): gather relu(seq) rows into g_A + zero g_T rows
__global__ void k_claimprep(const int* __restrict__ spans, const float* __restrict__ seq) {
    int bi = blockIdx.x;
    int tid = threadIdx.x;
    if (bi < 512) {
        int i = bi * 256 + tid;
        int b = i >> 12;
        int si = clampi(spans[3*i], 0, SS-1);
        int ei = clampi(spans[3*i + 1], 0, SS-1);
        int wi = clampi(spans[3*i + 2], 0, 8);
        int rs = g_rank[(b << 9) + si];
        int re = g_rank[(b << 9) + ei];
        int key = -2;
        bool own;
        if (rs < RANKCAP && re < RANKCAP) {
            key = b * KEYS_PER_B + (rs * RANKCAP + re) * 9 + wi;
            own = (atomicCAS(&g_ckey[key], 0, i + 1) == 0);
        } else {
            own = true;
        }
        g_key[i] = key;
        if (own) {
            int ss = g_slotOfPos[(b << 9) + si];
            int se = g_slotOfPos[(b << 9) + ei];
            int slot = atomicAdd(&g_ucount, 1);
            g_uinfo[slot] = (unsigned)ss | ((unsigned)se << 14) | ((unsigned)wi << 28);
            if (key >= 0) g_uslot[key] = slot;
            else g_spanslot[i] = slot;
        }
    } else {
        int cnt = g_count;
        for (int slot = bi - 512; slot < cnt; slot += 64) {
            int pos = g_list[slot];
            const float4* src = (const float4*)(seq + (size_t)pos * HH);
            float4* dst = (float4*)(g_A + (size_t)slot * HH);
            for (int t = tid; t < HH/4; t += 256) {
                float4 v = src[t];
                v.x = fmaxf(v.x, 0.f); v.y = fmaxf(v.y, 0.f);
                v.z = fmaxf(v.z, 0.f); v.w = fmaxf(v.w, 0.f);
                dst[t] = v;
            }
            float4* tz = (float4*)(g_T + (size_t)slot * T_STRIDE);
            for (int t = tid; t < T_STRIDE/4; t += 256) {
                tz[t] = make_float4(0.f, 0.f, 0.f, 0.f);
            }
        }
    }
}

// K4: T-projection GEMM (split-K x4, 8-row tiles) + WD tasks appended
__global__ void __launch_bounds__(320)
k_TgemmWD(const float* __restrict__ W1, const float* __restrict__ wt,
          const float* __restrict__ b1) {
    __shared__ float sA[8 * 192];
    int cnt = g_count;
    int ngemm = ((cnt + 7) >> 3) * 4;
    int ntasks = ngemm + 9;
    int tid = threadIdx.x;
    int jj = tid;
    const float* wp = (jj < 150) ? (W1 + jj) : (W1 + HH * WE + (jj - 150));

    for (int task = blockIdx.x; task < ntasks; task += gridDim.x) {
        if (task < ngemm) {
            int rt = task >> 2, ks = task & 3;
            int r0 = rt * 8, k0 = ks * 192;
            for (int idx = tid; idx < 8 * 192; idx += 320) {
                int lr = idx / 192, lk = idx - lr * 192;
                int row = r0 + lr;
                sA[idx] = (row < cnt) ? g_A[(size_t)row * HH + k0 + lk] : 0.f;
            }
            __syncthreads();
            if (jj < 300) {
                float acc[8];
                #pragma unroll
                for (int r = 0; r < 8; r++) acc[r] = 0.f;
                #pragma unroll 4
                for (int k = 0; k < 192; k++) {
                    float w1 = wp[(size_t)(k0 + k) * WE];
                    #pragma unroll
                    for (int r = 0; r < 8; r++)
                        acc[r] = fmaf(sA[r * 192 + k], w1, acc[r]);
                }
                int col = (jj < 150) ? jj : (152 + jj - 150);
                int rmax = min(8, cnt - r0);
                for (int r = 0; r < rmax; r++)
                    atomicAdd(&g_T[(size_t)(r0 + r) * T_STRIDE + col], acc[r]);
            }
            __syncthreads();
        } else {
            int w = task - ngemm;   // 0..8
            for (int t = tid; t < 150; t += 320) sA[t] = fmaxf(wt[w*150 + t], 0.f);
            __syncthreads();
            if (tid < 150) {
                float acc = b1[tid];
                #pragma unroll 5
                for (int k = 0; k < 150; k++)
                    acc = fmaf(sA[k], W1[(size_t)(2*HH + k) * WE + tid], acc);
                g_WD[w * WD_STRIDE + tid] = acc;
            }
            __syncthreads();
        }
    }
}

// K5: unique rows -> h1 -> @W2+b2 (FFMA2) -> @W3+b3 -> g_ULOG
// 64-row tiles, persistent grid of 148.
#define UT 64
__global__ void __launch_bounds__(256, 1)
k_uniq(const float* __restrict__ W2, const float* __restrict__ b2,
       const float* __restrict__ W3, const float* __restrict__ b3)
{
    extern __shared__ float sm[];
    float* sW2 = sm;                     // [150][160]
    float* sU  = sm + 24000;             // union: h1T [152][64] / h2 [64][164]
    float* sW3 = sm + 34496;             // [150][12]
    float* sB2 = sm + 36296;             // [160]
    float* sB3 = sm + 36456;             // [12]
    unsigned* sInfo = (unsigned*)(sm + 36468);  // [64]
    int tid = threadIdx.x;

    for (int idx = tid; idx < 150*160; idx += 256) {
        int k = idx / 160, j = idx - k*160;
        sW2[idx] = (j < 150) ? W2[k*150 + j] : 0.f;
    }
    for (int idx = tid; idx < 150*12; idx += 256) {
        int k = idx / 12, l = idx - k*12;
        sW3[idx] = (l < 9) ? W3[k*9 + l] : 0.f;
    }
    if (tid < 160) sB2[tid] = (tid < 150) ? b2[tid] : 0.f;
    if (tid < 12)  sB3[tid] = (tid < 9)  ? b3[tid] : 0.f;

    int nu = g_ucount;
    int r0 = (tid & 15) * 4;     // 4 consecutive rows
    int c0 = (tid >> 4) * 10;    // 10 cols = 5 packed pairs

    for (int base = blockIdx.x * UT; base < nu; base += gridDim.x * UT) {
        if (tid < UT)
            sInfo[tid] = (base + tid < nu) ? g_uinfo[base + tid] : 0u;
        __syncthreads();

        // gather h1, k-major [k][64], float4 over k
        for (int idx = tid; idx < 38*64; idx += 256) {
            int kq = idx >> 6, r = idx & 63;
            unsigned info = sInfo[r];
            int ss = info & 0x3FFF, se = (info >> 14) & 0x3FFF, w = info >> 28;
            float4 ts = *(const float4*)&g_T[(size_t)ss*T_STRIDE + kq*4];
            float4 te = *(const float4*)&g_T[(size_t)se*T_STRIDE + 152 + kq*4];
            float4 wd = *(const float4*)&g_WD[w*WD_STRIDE + kq*4];
            sU[(kq*4 + 0)*64 + r] = fmaxf(ts.x + te.x + wd.x, 0.f);
            sU[(kq*4 + 1)*64 + r] = fmaxf(ts.y + te.y + wd.y, 0.f);
            sU[(kq*4 + 2)*64 + r] = fmaxf(ts.z + te.z + wd.z, 0.f);
            sU[(kq*4 + 3)*64 + r] = fmaxf(ts.w + te.w + wd.w, 0.f);
        }
        __syncthreads();

        // h2 = h1 @ W2 + b2, packed column pairs (FFMA2)
        unsigned long long acc[4][5];
        {
            const unsigned long long* bp = (const unsigned long long*)&sB2[c0];
            #pragma unroll
            for (int p = 0; p < 5; p++) {
                unsigned long long bv = bp[p];
                #pragma unroll
                for (int ri = 0; ri < 4; ri++) acc[ri][p] = bv;
            }
        }
        #pragma unroll 2
        for (int k = 0; k < 150; k++) {
            float4 a = *(const float4*)&sU[k*64 + r0];
            unsigned long long ap[4] = {pack2(a.x), pack2(a.y), pack2(a.z), pack2(a.w)};
            const unsigned long long* bw = (const unsigned long long*)&sW2[k*160 + c0];
            unsigned long long bv[5] = {bw[0], bw[1], bw[2], bw[3], bw[4]};
            #pragma unroll
            for (int ri = 0; ri < 4; ri++)
                #pragma unroll
                for (int p = 0; p < 5; p++)
                    acc[ri][p] = ffma2(ap[ri], bv[p], acc[ri][p]);
        }
        __syncthreads();   // all h1 reads done before overwriting sU

        #pragma unroll
        for (int ri = 0; ri < 4; ri++)
            #pragma unroll
            for (int p = 0; p < 5; p++)
                *(unsigned long long*)&sU[(r0 + ri)*164 + c0 + 2*p] = acc[ri][p];
        __syncthreads();

        // logits = h2 @ W3 + b3
        for (int idx = tid; idx < UT*LL; idx += 256) {
            int r = idx / LL, l = idx - r*LL;
            float a = sB3[l];
            #pragma unroll 5
            for (int k = 0; k < 150; k++)
                a = fmaf(sU[r*164 + k], sW3[k*12 + l], a);
            if (base + r < nu)
                g_ULOG[(size_t)(base + r)*12 + l] = a;
        }
        __syncthreads();
    }
}

// K6: scatter logits per span + NLL loss + restore global state invariants
__global__ void k_scatter(const int* __restrict__ mask,
                          const int* __restrict__ label,
                          float* __restrict__ out)
{
    __shared__ float sL;
    if (threadIdx.x == 0) sL = 0.f;
    __syncthreads();
    int i = blockIdx.x * blockDim.x + threadIdx.x;
    float contrib = 0.f;
    if (i < NSPANS) {
        int key = g_key[i];
        int slot;
        if (key >= 0) { slot = g_uslot[key]; g_ckey[key] = 0; }
        else          { slot = g_spanslot[i]; }
        const float* Lr = &g_ULOG[(size_t)slot * 12];
        float4 p0 = *(const float4*)Lr;
        float4 p1 = *(const float4*)(Lr + 4);
        float l8 = Lr[8];
        float L[9] = {p0.x, p0.y, p0.z, p0.w, p1.x, p1.y, p1.z, p1.w, l8};
        float* o = out + (size_t)i * LL;
        #pragma unroll
        for (int l = 0; l < LL; l++) o[l] = L[l];
        if (mask[i] == 1) {
            float m = L[0];
            #pragma unroll
            for (int l = 1; l < LL; l++) m = fmaxf(m, L[l]);
            float ssum = 0.f;
            #pragma unroll
            for (int l = 0; l < LL; l++) ssum += expf(L[l] - m);
            int lb = clampi(label[i], 0, LL-1);
            contrib = (m + logf(ssum)) - L[lb];
        }
    }
    atomicAdd(&sL, contrib);
    __syncthreads();
    if (threadIdx.x == 0 && sL != 0.f)
        atomicAdd(&out[(size_t)NSPANS * LL], sL);
    if (blockIdx.x == 0 && threadIdx.x == 0) {
        g_count = 0; g_ucount = 0;
        #pragma unroll
        for (int w = 0; w < BB; w++) g_bcount[w] = 0;
    }
}

extern "C" void kernel_launch(void* const* d_in, const int* in_sizes, int n_in,
                              void* d_out, int out_size) {
    const float* seq = (const float*)d_in[0];
    const float* wt  = (const float*)d_in[1];
    const float* W1  = (const float*)d_in[2];
    const float* b1  = (const float*)d_in[3];
    const float* W2  = (const float*)d_in[4];
    const float* b2  = (const float*)d_in[5];
    const float* W3  = (const float*)d_in[6];
    const float* b3  = (const float*)d_in[7];
    const int* spans = (const int*)d_in[8];
    const int* smask = (const int*)d_in[9];
    const int* slab  = (const int*)d_in[10];
    float* out = (float*)d_out;

    static const size_t SMEM_UNIQ = (size_t)(36468 + 64) * 4;   // 146128 B
    cudaFuncSetAttribute(k_uniq, cudaFuncAttributeMaxDynamicSharedMemorySize, (int)SMEM_UNIQ);

    k_mark<<<NSPANS/256, 256>>>(spans, out + (size_t)NSPANS * LL);
    k_compact<<<NPOS/256, 256>>>();
    k_claimprep<<<576, 256>>>(spans, seq);
    k_TgemmWD<<<296, 320>>>(W1, wt, b1);
    k_uniq<<<148, 256, SMEM_UNIQ>>>(W2, b2, W3, b3);
    k_scatter<<<NSPANS/256, 256>>>(smask, slab, out);
}